// round 13
// baseline (speedup 1.0000x reference)
#include <cuda_runtime.h>
#include <cuda_fp16.h>
#include <math.h>

#define N_NODES 100000
#define N_EDGES 1600000
#define N_GRAPHS 2000
#define IN_C 9
#define HID 256
#define OUTF 128
#define BN_EPS 1e-5f

#define SCAN_B 1024
#define SCAN_NB ((N_NODES + SCAN_B - 1) / SCAN_B)   // 98

// ---------------- scratch ----------------
__device__ float g_dinv[N_NODES];
__device__ int   g_cnt[N_NODES];
__device__ int   g_rowptr[N_NODES + 1];
__device__ int   g_bsum[SCAN_NB];
__device__ int   g_csr_src[N_EDGES];
__device__ float g_xp[N_NODES * IN_C];
__device__ float g_xa[N_NODES * IN_C];
__device__ __align__(16) __half g_h1h[N_NODES * HID];
__device__ __align__(16) __half g_zh [N_NODES * OUTF];
__device__ __align__(16) float  g_h2[N_NODES * OUTF];
__device__ float g_stat1[2 * HID];
__device__ float g_stat2[2 * OUTF];
__device__ int   g_gstart[N_GRAPHS + 1];

// ---------------- helpers ----------------
__device__ __forceinline__ unsigned f2tf(float f) {
    unsigned r;
    asm("cvt.rna.tf32.f32 %0, %1;" : "=r"(r) : "f"(f));
    return r;
}
__device__ __forceinline__ void mma_tf32(float* d, const unsigned* a, const unsigned* b) {
    asm volatile(
        "mma.sync.aligned.m16n8k8.row.col.f32.tf32.tf32.f32 "
        "{%0,%1,%2,%3}, {%4,%5,%6,%7}, {%8,%9}, {%0,%1,%2,%3};"
        : "+f"(d[0]), "+f"(d[1]), "+f"(d[2]), "+f"(d[3])
        : "r"(a[0]), "r"(a[1]), "r"(a[2]), "r"(a[3]), "r"(b[0]), "r"(b[1]));
}

// ---------------- kernels ----------------

__global__ void k_init() {
    int i = blockIdx.x * blockDim.x + threadIdx.x;
    if (i < N_NODES) g_cnt[i] = 0;
    if (i < 2 * HID) g_stat1[i] = 0.f;
    if (i < 2 * OUTF) g_stat2[i] = 0.f;
}

// 4 edges per thread via int4
__global__ void k_count(const int* __restrict__ edge) {
    int q = blockIdx.x * blockDim.x + threadIdx.x;
    int e4 = q * 4;
    if (e4 >= N_EDGES) return;
    int4 d = *reinterpret_cast<const int4*>(&edge[N_EDGES + e4]);
    atomicAdd(&g_cnt[d.x], 1);
    atomicAdd(&g_cnt[d.y], 1);
    atomicAdd(&g_cnt[d.z], 1);
    atomicAdd(&g_cnt[d.w], 1);
}

__global__ __launch_bounds__(SCAN_B) void k_scan1() {
    __shared__ int sh[SCAN_B];
    int t = threadIdx.x;
    int i = blockIdx.x * SCAN_B + t;
    int c = (i < N_NODES) ? g_cnt[i] : 0;
    if (i < N_NODES) g_dinv[i] = rsqrtf((float)(c + 1));
    sh[t] = c;
    __syncthreads();
#pragma unroll
    for (int off = 1; off < SCAN_B; off <<= 1) {
        int v = sh[t];
        int add = (t >= off) ? sh[t - off] : 0;
        __syncthreads();
        sh[t] = v + add;
        __syncthreads();
    }
    if (i < N_NODES) g_rowptr[i] = sh[t] - c;
    if (t == SCAN_B - 1) g_bsum[blockIdx.x] = sh[t];
}

__global__ void k_scan2() {
    __shared__ int sh[128];
    int t = threadIdx.x;
    int v = (t < SCAN_NB) ? g_bsum[t] : 0;
    sh[t] = v;
    __syncthreads();
#pragma unroll
    for (int off = 1; off < 128; off <<= 1) {
        int x = sh[t];
        int add = (t >= off) ? sh[t - off] : 0;
        __syncthreads();
        sh[t] = x + add;
        __syncthreads();
    }
    if (t < SCAN_NB) g_bsum[t] = sh[t] - v;
}

__global__ __launch_bounds__(SCAN_B) void k_scan3(const float* __restrict__ x) {
    int i = blockIdx.x * SCAN_B + threadIdx.x;
    if (i < N_NODES) {
        int rp = g_rowptr[i] + g_bsum[blockIdx.x];
        g_rowptr[i] = rp;
        g_cnt[i] = rp;
        float dn = g_dinv[i];
        const float* xr = x + (long)i * IN_C;
        float* xw = g_xp + (long)i * IN_C;
#pragma unroll
        for (int k = 0; k < IN_C; k++) xw[k] = dn * xr[k];
    }
    if (i == 0) g_rowptr[N_NODES] = N_EDGES;
}

// fill CSR: 4 edges/thread via int4; fused gstart on the same grid
__global__ void k_fill(const int* __restrict__ edge, const int* __restrict__ batch) {
    int q = blockIdx.x * blockDim.x + threadIdx.x;
    int e4 = q * 4;
    if (e4 < N_EDGES) {
        int4 s = *reinterpret_cast<const int4*>(&edge[e4]);
        int4 d = *reinterpret_cast<const int4*>(&edge[N_EDGES + e4]);
        int p0 = atomicAdd(&g_cnt[d.x], 1); g_csr_src[p0] = s.x;
        int p1 = atomicAdd(&g_cnt[d.y], 1); g_csr_src[p1] = s.y;
        int p2 = atomicAdd(&g_cnt[d.z], 1); g_csr_src[p2] = s.z;
        int p3 = atomicAdd(&g_cnt[d.w], 1); g_csr_src[p3] = s.w;
    }
    if (q <= N_NODES) {
        int b = (q < N_NODES) ? batch[q] : N_GRAPHS;
        int bp = (q > 0) ? batch[q - 1] : -1;
        for (int g = bp + 1; g <= b && g <= N_GRAPHS; g++) g_gstart[g] = q;
    }
}

// xa[n] = dinv[n]*(sum x'[sn] + x'[n]); 2-edge batched gathers
__global__ void k_agg1() {
    int n = blockIdx.x * blockDim.x + threadIdx.x;
    if (n >= N_NODES) return;
    float acc[IN_C];
    const float* xn = g_xp + (long)n * IN_C;
#pragma unroll
    for (int k = 0; k < IN_C; k++) acc[k] = xn[k];
    int s = g_rowptr[n], e = g_rowptr[n + 1];
    int p = s;
    for (; p + 2 <= e; p += 2) {
        int s0 = g_csr_src[p], s1 = g_csr_src[p + 1];
        const float* x0 = g_xp + (long)s0 * IN_C;
        const float* x1 = g_xp + (long)s1 * IN_C;
#pragma unroll
        for (int k = 0; k < IN_C; k++) acc[k] += x0[k] + x1[k];
    }
    for (; p < e; p++) {
        const float* xr = g_xp + (long)g_csr_src[p] * IN_C;
#pragma unroll
        for (int k = 0; k < IN_C; k++) acc[k] += xr[k];
    }
    float dn = g_dinv[n];
#pragma unroll
    for (int k = 0; k < IN_C; k++) g_xa[n * IN_C + k] = dn * acc[k];
}

// h1 = xa @ W1 + b1 (raw fp16), fused BN1 stats. 256 rows/block.
#define G1_ROWS 256
__global__ __launch_bounds__(256) void k_gemm1(const float* __restrict__ W1,
                                               const float* __restrict__ b1) {
    __shared__ float W1s[IN_C * HID];
    __shared__ float xas[G1_ROWS * IN_C];
    int t = threadIdx.x;
    int row0 = blockIdx.x * G1_ROWS;
    for (int i = t; i < IN_C * HID; i += 256) W1s[i] = W1[i];
    for (int i = t; i < G1_ROWS * IN_C; i += 256) {
        int r = row0 + i / IN_C;
        xas[i] = (r < N_NODES) ? g_xa[(long)r * IN_C + (i % IN_C)] : 0.f;
    }
    __syncthreads();
    float b1j = b1[t];
    float w[IN_C];
#pragma unroll
    for (int k = 0; k < IN_C; k++) w[k] = W1s[k * HID + t];
    float sum = 0.f, sq = 0.f;
    for (int r = 0; r < G1_ROWS; r++) {
        int row = row0 + r;
        if (row >= N_NODES) break;
        float h0 = b1j, h1 = 0.f, h2 = 0.f;
#pragma unroll
        for (int k = 0; k < IN_C; k += 3) {
            h0 += xas[r * IN_C + k] * w[k];
            if (k + 1 < IN_C) h1 += xas[r * IN_C + k + 1] * w[k + 1];
            if (k + 2 < IN_C) h2 += xas[r * IN_C + k + 2] * w[k + 2];
        }
        float h = h0 + h1 + h2;
        g_h1h[(long)row * HID + t] = __float2half(h);
        sum += h;
        sq += h * h;
    }
    atomicAdd(&g_stat1[t], sum);
    atomicAdd(&g_stat1[HID + t], sq);
}

// z' = dinv*(relu(bn1(h1)) @ W2); software-pipelined: next chunk's LDGs
// issued before the mma loop so global latency overlaps tensor work.
#define TCBM 128
#define TCBK 32
#define AS_S 36
#define BS_S 136
__global__ __launch_bounds__(256) void k_gemm2(const float* __restrict__ W2,
                                               const float* __restrict__ g1,
                                               const float* __restrict__ be1) {
    __shared__ unsigned As[TCBM * AS_S];
    __shared__ unsigned Bs[TCBK * BS_S];
    __shared__ float s1s[HID], t1s[HID];
    const int t = threadIdx.x;
    const int lane = t & 31;
    const int wid = t >> 5;
    const int gid = lane >> 2;
    const int t4 = lane & 3;
    const int warp_row = (wid & 3) * 32;
    const int warp_col = (wid >> 2) * 64;
    const int row0 = blockIdx.x * TCBM;

    {
        float mean = g_stat1[t] / (float)N_NODES;
        float var = g_stat1[HID + t] / (float)N_NODES - mean * mean;
        var = fmaxf(var, 0.f);
        float sc = rsqrtf(var + BN_EPS) * g1[t];
        s1s[t] = sc;
        t1s[t] = be1[t] - mean * sc;
    }

    // per-thread load coordinates (fixed across chunks)
    const int arow = t >> 1;                 // A: 2 slots -> rows 0..127, halves
    const int acol8 = (t & 1) * 16;          // covers 32 halves in 2 uint4s? no:
    // A layout: each thread loads 2 uint4 (16 halves) -> thread covers row (t>>1),
    // halves [ (t&1)*16, (t&1)*16+16 )
    const int grow = row0 + arow;
    const long abase = (long)grow * HID;

    uint4 aR[2];
    float4 bR[4];

    // prologue loads (kt = 0)
#pragma unroll
    for (int u = 0; u < 2; u++) {
        int kg = acol8 + u * 8;              // half offset within 32-chunk
        aR[u] = (grow < N_NODES)
            ? *reinterpret_cast<const uint4*>(&g_h1h[abase + 0 * TCBK + kg])
            : make_uint4(0u, 0u, 0u, 0u);
    }
#pragma unroll
    for (int it = 0; it < 4; it++) {
        int q = t + it * 256;
        int kb = q >> 5;
        int col4 = (q & 31) * 4;
        bR[it] = *reinterpret_cast<const float4*>(&W2[(long)(0 * TCBK + kb) * OUTF + col4]);
    }

    float acc[2][8][4];
#pragma unroll
    for (int r = 0; r < 2; r++)
#pragma unroll
        for (int c = 0; c < 8; c++)
#pragma unroll
            for (int i = 0; i < 4; i++) acc[r][c][i] = 0.f;
    __syncthreads();

    for (int kt = 0; kt < HID / TCBK; kt++) {
        // store staged regs to smem (A: BN+relu+tf32, B: tf32)
#pragma unroll
        for (int u = 0; u < 2; u++) {
            int col8 = acol8 + u * 8;
            int kg = kt * TCBK + col8;
            const __half2* hp = reinterpret_cast<const __half2*>(&aR[u]);
#pragma unroll
            for (int v = 0; v < 4; v++) {
                float2 f = __half22float2(hp[v]);
                int k0 = kg + v * 2;
                As[arow * AS_S + col8 + v * 2 + 0] =
                    f2tf(fmaxf(f.x * s1s[k0 + 0] + t1s[k0 + 0], 0.f));
                As[arow * AS_S + col8 + v * 2 + 1] =
                    f2tf(fmaxf(f.y * s1s[k0 + 1] + t1s[k0 + 1], 0.f));
            }
        }
#pragma unroll
        for (int it = 0; it < 4; it++) {
            int q = t + it * 256;
            int kb = q >> 5;
            int col4 = (q & 31) * 4;
            Bs[kb * BS_S + col4 + 0] = f2tf(bR[it].x);
            Bs[kb * BS_S + col4 + 1] = f2tf(bR[it].y);
            Bs[kb * BS_S + col4 + 2] = f2tf(bR[it].z);
            Bs[kb * BS_S + col4 + 3] = f2tf(bR[it].w);
        }
        __syncthreads();

        // issue next chunk's global loads (overlap with mma below)
        if (kt + 1 < HID / TCBK) {
#pragma unroll
            for (int u = 0; u < 2; u++) {
                int kg = acol8 + u * 8;
                aR[u] = (grow < N_NODES)
                    ? *reinterpret_cast<const uint4*>(&g_h1h[abase + (kt + 1) * TCBK + kg])
                    : make_uint4(0u, 0u, 0u, 0u);
            }
#pragma unroll
            for (int it = 0; it < 4; it++) {
                int q = t + it * 256;
                int kb = q >> 5;
                int col4 = (q & 31) * 4;
                bR[it] = *reinterpret_cast<const float4*>(
                    &W2[(long)((kt + 1) * TCBK + kb) * OUTF + col4]);
            }
        }

#pragma unroll
        for (int ks = 0; ks < TCBK / 8; ks++) {
            unsigned a[2][4], b[8][2];
#pragma unroll
            for (int r = 0; r < 2; r++) {
                int rb = (warp_row + r * 16 + gid) * AS_S + ks * 8 + t4;
                a[r][0] = As[rb];
                a[r][1] = As[rb + 8 * AS_S];
                a[r][2] = As[rb + 4];
                a[r][3] = As[rb + 8 * AS_S + 4];
            }
#pragma unroll
            for (int c = 0; c < 8; c++) {
                int cb = (ks * 8 + t4) * BS_S + warp_col + c * 8 + gid;
                b[c][0] = Bs[cb];
                b[c][1] = Bs[cb + 4 * BS_S];
            }
#pragma unroll
            for (int r = 0; r < 2; r++)
#pragma unroll
                for (int c = 0; c < 8; c++) mma_tf32(acc[r][c], a[r], b[c]);
        }
        __syncthreads();
    }
#pragma unroll
    for (int r = 0; r < 2; r++) {
        int rowA = row0 + warp_row + r * 16 + gid;
        int rowB = rowA + 8;
        float dA = (rowA < N_NODES) ? g_dinv[rowA] : 0.f;
        float dB = (rowB < N_NODES) ? g_dinv[rowB] : 0.f;
#pragma unroll
        for (int c = 0; c < 8; c++) {
            int col = warp_col + c * 8 + t4 * 2;
            if (rowA < N_NODES)
                *reinterpret_cast<__half2*>(&g_zh[(long)rowA * OUTF + col]) =
                    __floats2half2_rn(dA * acc[r][c][0], dA * acc[r][c][1]);
            if (rowB < N_NODES)
                *reinterpret_cast<__half2*>(&g_zh[(long)rowB * OUTF + col]) =
                    __floats2half2_rn(dB * acc[r][c][2], dB * acc[r][c][3]);
        }
    }
}

// agg2: 8-edge unrolled gathers (explicit scalars), fused BN2 stats
#define A2_NPB 8
__global__ __launch_bounds__(128) void k_agg2(const float* __restrict__ b2) {
    int j = threadIdx.x;
    int n0 = blockIdx.x * A2_NPB;
    float b2j = b2[j];
    float bs = 0.f, bq = 0.f;
#pragma unroll 1
    for (int u = 0; u < A2_NPB; u++) {
        int n = n0 + u;
        int s = g_rowptr[n], e = g_rowptr[n + 1];
        float acc = __half2float(g_zh[(long)n * OUTF + j]);
        int p = s;
        for (; p + 8 <= e; p += 8) {
            int s0 = g_csr_src[p + 0], s1 = g_csr_src[p + 1];
            int s2 = g_csr_src[p + 2], s3 = g_csr_src[p + 3];
            int s4 = g_csr_src[p + 4], s5 = g_csr_src[p + 5];
            int s6 = g_csr_src[p + 6], s7 = g_csr_src[p + 7];
            float z0 = __half2float(g_zh[(long)s0 * OUTF + j]);
            float z1 = __half2float(g_zh[(long)s1 * OUTF + j]);
            float z2 = __half2float(g_zh[(long)s2 * OUTF + j]);
            float z3 = __half2float(g_zh[(long)s3 * OUTF + j]);
            float z4 = __half2float(g_zh[(long)s4 * OUTF + j]);
            float z5 = __half2float(g_zh[(long)s5 * OUTF + j]);
            float z6 = __half2float(g_zh[(long)s6 * OUTF + j]);
            float z7 = __half2float(g_zh[(long)s7 * OUTF + j]);
            acc += ((z0 + z1) + (z2 + z3)) + ((z4 + z5) + (z6 + z7));
        }
        for (; p < e; p++)
            acc += __half2float(g_zh[(long)g_csr_src[p] * OUTF + j]);
        float dn = g_dinv[n];
        float val = dn * acc + b2j;
        g_h2[(long)n * OUTF + j] = val;
        bs += val;
        bq += val * val;
    }
    atomicAdd(&g_stat2[j], bs);
    atomicAdd(&g_stat2[OUTF + j], bq);
}

// pool + BN2 affine + L2 normalize
__global__ __launch_bounds__(128) void k_pool(const float* __restrict__ g2,
                                              const float* __restrict__ be2,
                                              float* __restrict__ out) {
    int g = blockIdx.x;
    int j = threadIdx.x;
    float mean = g_stat2[j] / (float)N_NODES;
    float var = g_stat2[OUTF + j] / (float)N_NODES - mean * mean;
    var = fmaxf(var, 0.f);
    float sc = rsqrtf(var + BN_EPS) * g2[j];
    float sh = be2[j] - mean * sc;
    int s = g_gstart[g], e = g_gstart[g + 1];
    float acc = 0.f;
    for (int i = s; i < e; i++) acc += g_h2[(long)i * OUTF + j];
    int cnt = e - s;
    float y = 0.f;
    if (cnt > 0) {
        float p = acc / (float)cnt;
        y = p * sc + sh;
    }
    float v = y * y;
#pragma unroll
    for (int off = 16; off > 0; off >>= 1) v += __shfl_xor_sync(0xffffffffu, v, off);
    __shared__ float ws[4];
    if ((j & 31) == 0) ws[j >> 5] = v;
    __syncthreads();
    float ss = ws[0] + ws[1] + ws[2] + ws[3];
    float nrm = sqrtf(ss);
    out[g * OUTF + j] = y / fmaxf(nrm, 1e-12f);
}

// ---------------- launch ----------------
extern "C" void kernel_launch(void* const* d_in, const int* in_sizes, int n_in,
                              void* d_out, int out_size) {
    const float* x   = (const float*)d_in[0];
    const float* W1  = (const float*)d_in[1];
    const float* b1  = (const float*)d_in[2];
    const float* g1  = (const float*)d_in[3];
    const float* be1 = (const float*)d_in[4];
    const float* W2  = (const float*)d_in[5];
    const float* b2  = (const float*)d_in[6];
    const float* g2  = (const float*)d_in[7];
    const float* be2 = (const float*)d_in[8];
    const int* edge  = (const int*)d_in[9];
    const int* batch = (const int*)d_in[10];
    float* out = (float*)d_out;

    const int TB = 256;
    int nb_N = (N_NODES + TB - 1) / TB;
    int nb_E4 = (N_EDGES / 4 + TB - 1) / TB;
    int nb_fill = ((N_NODES + 1 > N_EDGES / 4 ? N_NODES + 1 : N_EDGES / 4) + TB - 1) / TB;

    k_init<<<nb_N, TB>>>();
    k_count<<<nb_E4, TB>>>(edge);
    k_scan1<<<SCAN_NB, SCAN_B>>>();
    k_scan2<<<1, 128>>>();
    k_scan3<<<SCAN_NB, SCAN_B>>>(x);
    k_fill<<<nb_fill, TB>>>(edge, batch);
    k_agg1<<<nb_N, TB>>>();
    k_gemm1<<<(N_NODES + G1_ROWS - 1) / G1_ROWS, 256>>>(W1, b1);
    k_gemm2<<<(N_NODES + TCBM - 1) / TCBM, 256>>>(W2, g1, be1);
    k_agg2<<<N_NODES / A2_NPB, 128>>>(b2);
    k_pool<<<N_GRAPHS, 128>>>(g2, be2, out);
}

// round 14
// speedup vs baseline: 1.0979x; 1.0979x over previous
#include <cuda_runtime.h>
#include <cuda_fp16.h>
#include <math.h>

#define N_NODES 100000
#define N_EDGES 1600000
#define N_GRAPHS 2000
#define IN_C 9
#define HID 256
#define OUTF 128
#define BN_EPS 1e-5f

#define SCAN_B 1024
#define SCAN_NB ((N_NODES + SCAN_B - 1) / SCAN_B)   // 98

// ---------------- scratch ----------------
__device__ float g_dinv[N_NODES];
__device__ int   g_cnt[N_NODES];
__device__ int   g_rowptr[N_NODES + 1];
__device__ int   g_bsum[SCAN_NB];
__device__ int   g_csr_src[N_EDGES];
__device__ float g_xp[N_NODES * IN_C];
__device__ float g_xa[N_NODES * IN_C];
__device__ __align__(16) __half g_h1h[N_NODES * HID];
__device__ __align__(16) __half g_zh [N_NODES * OUTF];
__device__ __align__(16) float  g_h2[N_NODES * OUTF];
__device__ float g_stat1[2 * HID];
__device__ float g_stat2[2 * OUTF];
__device__ int   g_gstart[N_GRAPHS + 1];

// ---------------- helpers ----------------
__device__ __forceinline__ unsigned f2tf(float f) {
    unsigned r;
    asm("cvt.rna.tf32.f32 %0, %1;" : "=r"(r) : "f"(f));
    return r;
}
__device__ __forceinline__ void mma_tf32(float* d, const unsigned* a, const unsigned* b) {
    asm volatile(
        "mma.sync.aligned.m16n8k8.row.col.f32.tf32.tf32.f32 "
        "{%0,%1,%2,%3}, {%4,%5,%6,%7}, {%8,%9}, {%0,%1,%2,%3};"
        : "+f"(d[0]), "+f"(d[1]), "+f"(d[2]), "+f"(d[3])
        : "r"(a[0]), "r"(a[1]), "r"(a[2]), "r"(a[3]), "r"(b[0]), "r"(b[1]));
}

// ---------------- kernels ----------------

__global__ void k_init() {
    int i = blockIdx.x * blockDim.x + threadIdx.x;
    if (i < N_NODES) g_cnt[i] = 0;
    if (i < 2 * HID) g_stat1[i] = 0.f;
    if (i < 2 * OUTF) g_stat2[i] = 0.f;
}

// 4 edges per thread via int4 (N_EDGES divisible by 4)
__global__ void k_count(const int* __restrict__ edge) {
    int q = blockIdx.x * blockDim.x + threadIdx.x;
    int e4 = q * 4;
    if (e4 >= N_EDGES) return;
    int4 d = *reinterpret_cast<const int4*>(&edge[N_EDGES + e4]);
    atomicAdd(&g_cnt[d.x], 1);
    atomicAdd(&g_cnt[d.y], 1);
    atomicAdd(&g_cnt[d.z], 1);
    atomicAdd(&g_cnt[d.w], 1);
}

__global__ __launch_bounds__(SCAN_B) void k_scan1() {
    __shared__ int sh[SCAN_B];
    int t = threadIdx.x;
    int i = blockIdx.x * SCAN_B + t;
    int c = (i < N_NODES) ? g_cnt[i] : 0;
    if (i < N_NODES) g_dinv[i] = rsqrtf((float)(c + 1));
    sh[t] = c;
    __syncthreads();
#pragma unroll
    for (int off = 1; off < SCAN_B; off <<= 1) {
        int v = sh[t];
        int add = (t >= off) ? sh[t - off] : 0;
        __syncthreads();
        sh[t] = v + add;
        __syncthreads();
    }
    if (i < N_NODES) g_rowptr[i] = sh[t] - c;
    if (t == SCAN_B - 1) g_bsum[blockIdx.x] = sh[t];
}

__global__ void k_scan2() {
    __shared__ int sh[128];
    int t = threadIdx.x;
    int v = (t < SCAN_NB) ? g_bsum[t] : 0;
    sh[t] = v;
    __syncthreads();
#pragma unroll
    for (int off = 1; off < 128; off <<= 1) {
        int x = sh[t];
        int add = (t >= off) ? sh[t - off] : 0;
        __syncthreads();
        sh[t] = x + add;
        __syncthreads();
    }
    if (t < SCAN_NB) g_bsum[t] = sh[t] - v;
}

__global__ __launch_bounds__(SCAN_B) void k_scan3(const float* __restrict__ x) {
    int i = blockIdx.x * SCAN_B + threadIdx.x;
    if (i < N_NODES) {
        int rp = g_rowptr[i] + g_bsum[blockIdx.x];
        g_rowptr[i] = rp;
        g_cnt[i] = rp;
        float dn = g_dinv[i];
        const float* xr = x + (long)i * IN_C;
        float* xw = g_xp + (long)i * IN_C;
#pragma unroll
        for (int k = 0; k < IN_C; k++) xw[k] = dn * xr[k];
    }
    if (i == 0) g_rowptr[N_NODES] = N_EDGES;
}

// fill CSR: 4 edges/thread via int4; fused gstart on the same grid
__global__ void k_fill(const int* __restrict__ edge, const int* __restrict__ batch) {
    int q = blockIdx.x * blockDim.x + threadIdx.x;
    int e4 = q * 4;
    if (e4 < N_EDGES) {
        int4 s = *reinterpret_cast<const int4*>(&edge[e4]);
        int4 d = *reinterpret_cast<const int4*>(&edge[N_EDGES + e4]);
        int p0 = atomicAdd(&g_cnt[d.x], 1); g_csr_src[p0] = s.x;
        int p1 = atomicAdd(&g_cnt[d.y], 1); g_csr_src[p1] = s.y;
        int p2 = atomicAdd(&g_cnt[d.z], 1); g_csr_src[p2] = s.z;
        int p3 = atomicAdd(&g_cnt[d.w], 1); g_csr_src[p3] = s.w;
    }
    if (q <= N_NODES) {
        int b = (q < N_NODES) ? batch[q] : N_GRAPHS;
        int bp = (q > 0) ? batch[q - 1] : -1;
        for (int g = bp + 1; g <= b && g <= N_GRAPHS; g++) g_gstart[g] = q;
    }
}

// xa[n] = dinv[n] * (sum_{sn} x'[sn] + x'[n])   (R12 version)
__global__ void k_agg1() {
    int n = blockIdx.x * blockDim.x + threadIdx.x;
    if (n >= N_NODES) return;
    float acc[IN_C];
    const float* xn = g_xp + (long)n * IN_C;
#pragma unroll
    for (int k = 0; k < IN_C; k++) acc[k] = xn[k];
    int s = g_rowptr[n], e = g_rowptr[n + 1];
    for (int p = s; p < e; p++) {
        int sn = g_csr_src[p];
        const float* xr = g_xp + (long)sn * IN_C;
#pragma unroll
        for (int k = 0; k < IN_C; k++) acc[k] += xr[k];
    }
    float dn = g_dinv[n];
#pragma unroll
    for (int k = 0; k < IN_C; k++) g_xa[n * IN_C + k] = dn * acc[k];
}

// h1 = xa @ W1 + b1 (raw fp16), fused BN1 stats. 256 rows/block. (R12 version)
#define G1_ROWS 256
__global__ __launch_bounds__(256) void k_gemm1(const float* __restrict__ W1,
                                               const float* __restrict__ b1) {
    __shared__ float W1s[IN_C * HID];
    __shared__ float xas[G1_ROWS * IN_C];
    int t = threadIdx.x;
    int row0 = blockIdx.x * G1_ROWS;
    for (int i = t; i < IN_C * HID; i += 256) W1s[i] = W1[i];
    for (int i = t; i < G1_ROWS * IN_C; i += 256) {
        int r = row0 + i / IN_C;
        xas[i] = (r < N_NODES) ? g_xa[(long)r * IN_C + (i % IN_C)] : 0.f;
    }
    __syncthreads();
    float b1j = b1[t];
    float w[IN_C];
#pragma unroll
    for (int k = 0; k < IN_C; k++) w[k] = W1s[k * HID + t];
    float sum = 0.f, sq = 0.f;
    for (int r = 0; r < G1_ROWS; r++) {
        int row = row0 + r;
        if (row >= N_NODES) break;
        float h0 = b1j, h1 = 0.f, h2 = 0.f;
#pragma unroll
        for (int k = 0; k < IN_C; k += 3) {
            h0 += xas[r * IN_C + k] * w[k];
            if (k + 1 < IN_C) h1 += xas[r * IN_C + k + 1] * w[k + 1];
            if (k + 2 < IN_C) h2 += xas[r * IN_C + k + 2] * w[k + 2];
        }
        float h = h0 + h1 + h2;
        g_h1h[(long)row * HID + t] = __float2half(h);
        sum += h;
        sq += h * h;
    }
    atomicAdd(&g_stat1[t], sum);
    atomicAdd(&g_stat1[HID + t], sq);
}

// z' = dinv * (relu(bn1(h1)) @ W2); R12 version (no software pipeline)
#define TCBM 128
#define TCBK 32
#define AS_S 36
#define BS_S 136
__global__ __launch_bounds__(256) void k_gemm2(const float* __restrict__ W2,
                                               const float* __restrict__ g1,
                                               const float* __restrict__ be1) {
    __shared__ unsigned As[TCBM * AS_S];
    __shared__ unsigned Bs[TCBK * BS_S];
    __shared__ float s1s[HID], t1s[HID];
    const int t = threadIdx.x;
    const int lane = t & 31;
    const int wid = t >> 5;
    const int gid = lane >> 2;
    const int t4 = lane & 3;
    const int warp_row = (wid & 3) * 32;
    const int warp_col = (wid >> 2) * 64;
    const int row0 = blockIdx.x * TCBM;

    {
        float mean = g_stat1[t] / (float)N_NODES;
        float var = g_stat1[HID + t] / (float)N_NODES - mean * mean;
        var = fmaxf(var, 0.f);
        float sc = rsqrtf(var + BN_EPS) * g1[t];
        s1s[t] = sc;
        t1s[t] = be1[t] - mean * sc;
    }

    float acc[2][8][4];
#pragma unroll
    for (int r = 0; r < 2; r++)
#pragma unroll
        for (int c = 0; c < 8; c++)
#pragma unroll
            for (int i = 0; i < 4; i++) acc[r][c][i] = 0.f;
    __syncthreads();

    for (int kt = 0; kt < HID / TCBK; kt++) {
#pragma unroll
        for (int it = 0; it < 2; it++) {
            int q = t + it * 256;
            int row = q >> 2;
            int col8 = (q & 3) * 8;
            int kg = kt * TCBK + col8;
            int grow = row0 + row;
            uint4 raw = make_uint4(0u, 0u, 0u, 0u);
            if (grow < N_NODES)
                raw = *reinterpret_cast<const uint4*>(&g_h1h[(long)grow * HID + kg]);
            const __half2* hp = reinterpret_cast<const __half2*>(&raw);
#pragma unroll
            for (int u = 0; u < 4; u++) {
                float2 f = __half22float2(hp[u]);
                int k0 = kg + u * 2;
                As[row * AS_S + col8 + u * 2 + 0] =
                    f2tf(fmaxf(f.x * s1s[k0 + 0] + t1s[k0 + 0], 0.f));
                As[row * AS_S + col8 + u * 2 + 1] =
                    f2tf(fmaxf(f.y * s1s[k0 + 1] + t1s[k0 + 1], 0.f));
            }
        }
#pragma unroll
        for (int it = 0; it < 4; it++) {
            int q = t + it * 256;
            int kb = q >> 5;
            int col4 = (q & 31) * 4;
            float4 v = *reinterpret_cast<const float4*>(&W2[(long)(kt * TCBK + kb) * OUTF + col4]);
            Bs[kb * BS_S + col4 + 0] = f2tf(v.x);
            Bs[kb * BS_S + col4 + 1] = f2tf(v.y);
            Bs[kb * BS_S + col4 + 2] = f2tf(v.z);
            Bs[kb * BS_S + col4 + 3] = f2tf(v.w);
        }
        __syncthreads();
#pragma unroll
        for (int ks = 0; ks < TCBK / 8; ks++) {
            unsigned a[2][4], b[8][2];
#pragma unroll
            for (int r = 0; r < 2; r++) {
                int rb = (warp_row + r * 16 + gid) * AS_S + ks * 8 + t4;
                a[r][0] = As[rb];
                a[r][1] = As[rb + 8 * AS_S];
                a[r][2] = As[rb + 4];
                a[r][3] = As[rb + 8 * AS_S + 4];
            }
#pragma unroll
            for (int c = 0; c < 8; c++) {
                int cb = (ks * 8 + t4) * BS_S + warp_col + c * 8 + gid;
                b[c][0] = Bs[cb];
                b[c][1] = Bs[cb + 4 * BS_S];
            }
#pragma unroll
            for (int r = 0; r < 2; r++)
#pragma unroll
                for (int c = 0; c < 8; c++) mma_tf32(acc[r][c], a[r], b[c]);
        }
        __syncthreads();
    }
#pragma unroll
    for (int r = 0; r < 2; r++) {
        int rowA = row0 + warp_row + r * 16 + gid;
        int rowB = rowA + 8;
        float dA = (rowA < N_NODES) ? g_dinv[rowA] : 0.f;
        float dB = (rowB < N_NODES) ? g_dinv[rowB] : 0.f;
#pragma unroll
        for (int c = 0; c < 8; c++) {
            int col = warp_col + c * 8 + t4 * 2;
            if (rowA < N_NODES)
                *reinterpret_cast<__half2*>(&g_zh[(long)rowA * OUTF + col]) =
                    __floats2half2_rn(dA * acc[r][c][0], dA * acc[r][c][1]);
            if (rowB < N_NODES)
                *reinterpret_cast<__half2*>(&g_zh[(long)rowB * OUTF + col]) =
                    __floats2half2_rn(dB * acc[r][c][2], dB * acc[r][c][3]);
        }
    }
}

// agg2: R12 version (4-edge batch), fused BN2 stats
#define A2_NPB 8
__global__ __launch_bounds__(128) void k_agg2(const float* __restrict__ b2) {
    int j = threadIdx.x;
    int n0 = blockIdx.x * A2_NPB;
    float b2j = b2[j];
    float bs = 0.f, bq = 0.f;
#pragma unroll 1
    for (int u = 0; u < A2_NPB; u++) {
        int n = n0 + u;
        int s = g_rowptr[n], e = g_rowptr[n + 1];
        float acc = __half2float(g_zh[(long)n * OUTF + j]);
        int p = s;
        for (; p + 4 <= e; p += 4) {
            int s0 = g_csr_src[p + 0], s1 = g_csr_src[p + 1];
            int s2 = g_csr_src[p + 2], s3 = g_csr_src[p + 3];
            float z0 = __half2float(g_zh[(long)s0 * OUTF + j]);
            float z1 = __half2float(g_zh[(long)s1 * OUTF + j]);
            float z2 = __half2float(g_zh[(long)s2 * OUTF + j]);
            float z3 = __half2float(g_zh[(long)s3 * OUTF + j]);
            acc += z0 + z1 + z2 + z3;
        }
        for (; p < e; p++)
            acc += __half2float(g_zh[(long)g_csr_src[p] * OUTF + j]);
        float dn = g_dinv[n];
        float val = dn * acc + b2j;
        g_h2[(long)n * OUTF + j] = val;
        bs += val;
        bq += val * val;
    }
    atomicAdd(&g_stat2[j], bs);
    atomicAdd(&g_stat2[OUTF + j], bq);
}

// pool + BN2 affine + L2 normalize
__global__ __launch_bounds__(128) void k_pool(const float* __restrict__ g2,
                                              const float* __restrict__ be2,
                                              float* __restrict__ out) {
    int g = blockIdx.x;
    int j = threadIdx.x;
    float mean = g_stat2[j] / (float)N_NODES;
    float var = g_stat2[OUTF + j] / (float)N_NODES - mean * mean;
    var = fmaxf(var, 0.f);
    float sc = rsqrtf(var + BN_EPS) * g2[j];
    float sh = be2[j] - mean * sc;
    int s = g_gstart[g], e = g_gstart[g + 1];
    float acc = 0.f;
    for (int i = s; i < e; i++) acc += g_h2[(long)i * OUTF + j];
    int cnt = e - s;
    float y = 0.f;
    if (cnt > 0) {
        float p = acc / (float)cnt;
        y = p * sc + sh;
    }
    float v = y * y;
#pragma unroll
    for (int off = 16; off > 0; off >>= 1) v += __shfl_xor_sync(0xffffffffu, v, off);
    __shared__ float ws[4];
    if ((j & 31) == 0) ws[j >> 5] = v;
    __syncthreads();
    float ss = ws[0] + ws[1] + ws[2] + ws[3];
    float nrm = sqrtf(ss);
    out[g * OUTF + j] = y / fmaxf(nrm, 1e-12f);
}

// ---------------- launch ----------------
extern "C" void kernel_launch(void* const* d_in, const int* in_sizes, int n_in,
                              void* d_out, int out_size) {
    const float* x   = (const float*)d_in[0];
    const float* W1  = (const float*)d_in[1];
    const float* b1  = (const float*)d_in[2];
    const float* g1  = (const float*)d_in[3];
    const float* be1 = (const float*)d_in[4];
    const float* W2  = (const float*)d_in[5];
    const float* b2  = (const float*)d_in[6];
    const float* g2  = (const float*)d_in[7];
    const float* be2 = (const float*)d_in[8];
    const int* edge  = (const int*)d_in[9];
    const int* batch = (const int*)d_in[10];
    float* out = (float*)d_out;

    const int TB = 256;
    int nb_N = (N_NODES + TB - 1) / TB;
    int nb_E4 = (N_EDGES / 4 + TB - 1) / TB;
    int nb_fill = ((N_NODES + 1 > N_EDGES / 4 ? N_NODES + 1 : N_EDGES / 4) + TB - 1) / TB;

    k_init<<<nb_N, TB>>>();
    k_count<<<nb_E4, TB>>>(edge);
    k_scan1<<<SCAN_NB, SCAN_B>>>();
    k_scan2<<<1, 128>>>();
    k_scan3<<<SCAN_NB, SCAN_B>>>(x);
    k_fill<<<nb_fill, TB>>>(edge, batch);
    k_agg1<<<nb_N, TB>>>();
    k_gemm1<<<(N_NODES + G1_ROWS - 1) / G1_ROWS, 256>>>(W1, b1);
    k_gemm2<<<(N_NODES + TCBM - 1) / TCBM, 256>>>(W2, g1, be1);
    k_agg2<<<N_NODES / A2_NPB, 128>>>(b2);
    k_pool<<<N_GRAPHS, 128>>>(g2, be2, out);
}

// round 15
// speedup vs baseline: 1.0989x; 1.0010x over previous
#include <cuda_runtime.h>
#include <cuda_fp16.h>
#include <math.h>

#define N_NODES 100000
#define N_EDGES 1600000
#define N_GRAPHS 2000
#define IN_C 9
#define HID 256
#define OUTF 128
#define BN_EPS 1e-5f

#define SCAN_B 1024
#define SCAN_NB ((N_NODES + SCAN_B - 1) / SCAN_B)   // 98

// ---------------- scratch ----------------
__device__ float g_dinv[N_NODES];
__device__ int   g_cnt[N_NODES];
__device__ int   g_rowptr[N_NODES + 1];
__device__ int   g_bsum[SCAN_NB];
__device__ int   g_csr_src[N_EDGES];
__device__ float g_xp[N_NODES * IN_C];
__device__ float g_xa[N_NODES * IN_C];
__device__ __align__(16) __half g_h1h[N_NODES * HID];
__device__ __align__(16) __half g_zh [N_NODES * OUTF];
__device__ __align__(16) float  g_h2[N_NODES * OUTF];
__device__ float g_stat1[2 * HID];
__device__ float g_stat2[2 * OUTF];
__device__ int   g_gstart[N_GRAPHS + 1];

// ---------------- helpers ----------------
__device__ __forceinline__ unsigned f2tf(float f) {
    unsigned r;
    asm("cvt.rna.tf32.f32 %0, %1;" : "=r"(r) : "f"(f));
    return r;
}
__device__ __forceinline__ void mma_tf32(float* d, const unsigned* a, const unsigned* b) {
    asm volatile(
        "mma.sync.aligned.m16n8k8.row.col.f32.tf32.tf32.f32 "
        "{%0,%1,%2,%3}, {%4,%5,%6,%7}, {%8,%9}, {%0,%1,%2,%3};"
        : "+f"(d[0]), "+f"(d[1]), "+f"(d[2]), "+f"(d[3])
        : "r"(a[0]), "r"(a[1]), "r"(a[2]), "r"(a[3]), "r"(b[0]), "r"(b[1]));
}

// ---------------- kernels ----------------

__global__ void k_init() {
    int i = blockIdx.x * blockDim.x + threadIdx.x;
    if (i < N_NODES) g_cnt[i] = 0;
    if (i < 2 * HID) g_stat1[i] = 0.f;
    if (i < 2 * OUTF) g_stat2[i] = 0.f;
}

// 4 edges per thread via int4
__global__ void k_count(const int* __restrict__ edge) {
    int q = blockIdx.x * blockDim.x + threadIdx.x;
    int e4 = q * 4;
    if (e4 >= N_EDGES) return;
    int4 d = *reinterpret_cast<const int4*>(&edge[N_EDGES + e4]);
    atomicAdd(&g_cnt[d.x], 1);
    atomicAdd(&g_cnt[d.y], 1);
    atomicAdd(&g_cnt[d.z], 1);
    atomicAdd(&g_cnt[d.w], 1);
}

__global__ __launch_bounds__(SCAN_B) void k_scan1() {
    __shared__ int sh[SCAN_B];
    int t = threadIdx.x;
    int i = blockIdx.x * SCAN_B + t;
    int c = (i < N_NODES) ? g_cnt[i] : 0;
    if (i < N_NODES) g_dinv[i] = rsqrtf((float)(c + 1));
    sh[t] = c;
    __syncthreads();
#pragma unroll
    for (int off = 1; off < SCAN_B; off <<= 1) {
        int v = sh[t];
        int add = (t >= off) ? sh[t - off] : 0;
        __syncthreads();
        sh[t] = v + add;
        __syncthreads();
    }
    if (i < N_NODES) g_rowptr[i] = sh[t] - c;
    if (t == SCAN_B - 1) g_bsum[blockIdx.x] = sh[t];
}

__global__ void k_scan2() {
    __shared__ int sh[128];
    int t = threadIdx.x;
    int v = (t < SCAN_NB) ? g_bsum[t] : 0;
    sh[t] = v;
    __syncthreads();
#pragma unroll
    for (int off = 1; off < 128; off <<= 1) {
        int x = sh[t];
        int add = (t >= off) ? sh[t - off] : 0;
        __syncthreads();
        sh[t] = x + add;
        __syncthreads();
    }
    if (t < SCAN_NB) g_bsum[t] = sh[t] - v;
}

__global__ __launch_bounds__(SCAN_B) void k_scan3(const float* __restrict__ x) {
    int i = blockIdx.x * SCAN_B + threadIdx.x;
    if (i < N_NODES) {
        int rp = g_rowptr[i] + g_bsum[blockIdx.x];
        g_rowptr[i] = rp;
        g_cnt[i] = rp;
        float dn = g_dinv[i];
        const float* xr = x + (long)i * IN_C;
        float* xw = g_xp + (long)i * IN_C;
#pragma unroll
        for (int k = 0; k < IN_C; k++) xw[k] = dn * xr[k];
    }
    if (i == 0) g_rowptr[N_NODES] = N_EDGES;
}

// fill CSR: 4 edges/thread via int4; fused gstart on the same grid
__global__ void k_fill(const int* __restrict__ edge, const int* __restrict__ batch) {
    int q = blockIdx.x * blockDim.x + threadIdx.x;
    int e4 = q * 4;
    if (e4 < N_EDGES) {
        int4 s = *reinterpret_cast<const int4*>(&edge[e4]);
        int4 d = *reinterpret_cast<const int4*>(&edge[N_EDGES + e4]);
        int p0 = atomicAdd(&g_cnt[d.x], 1); g_csr_src[p0] = s.x;
        int p1 = atomicAdd(&g_cnt[d.y], 1); g_csr_src[p1] = s.y;
        int p2 = atomicAdd(&g_cnt[d.z], 1); g_csr_src[p2] = s.z;
        int p3 = atomicAdd(&g_cnt[d.w], 1); g_csr_src[p3] = s.w;
    }
    if (q <= N_NODES) {
        int b = (q < N_NODES) ? batch[q] : N_GRAPHS;
        int bp = (q > 0) ? batch[q - 1] : -1;
        for (int g = bp + 1; g <= b && g <= N_GRAPHS; g++) g_gstart[g] = q;
    }
}

// xa[n] = dinv[n] * (sum_{sn} x'[sn] + x'[n])
__global__ void k_agg1() {
    int n = blockIdx.x * blockDim.x + threadIdx.x;
    if (n >= N_NODES) return;
    float acc[IN_C];
    const float* xn = g_xp + (long)n * IN_C;
#pragma unroll
    for (int k = 0; k < IN_C; k++) acc[k] = xn[k];
    int s = g_rowptr[n], e = g_rowptr[n + 1];
    for (int p = s; p < e; p++) {
        int sn = g_csr_src[p];
        const float* xr = g_xp + (long)sn * IN_C;
#pragma unroll
        for (int k = 0; k < IN_C; k++) acc[k] += xr[k];
    }
    float dn = g_dinv[n];
#pragma unroll
    for (int k = 0; k < IN_C; k++) g_xa[n * IN_C + k] = dn * acc[k];
}

// h1 = xa @ W1 + b1 (raw fp16), fused BN1 stats. 256 rows/block.
#define G1_ROWS 256
__global__ __launch_bounds__(256) void k_gemm1(const float* __restrict__ W1,
                                               const float* __restrict__ b1) {
    __shared__ float W1s[IN_C * HID];
    __shared__ float xas[G1_ROWS * IN_C];
    int t = threadIdx.x;
    int row0 = blockIdx.x * G1_ROWS;
    for (int i = t; i < IN_C * HID; i += 256) W1s[i] = W1[i];
    for (int i = t; i < G1_ROWS * IN_C; i += 256) {
        int r = row0 + i / IN_C;
        xas[i] = (r < N_NODES) ? g_xa[(long)r * IN_C + (i % IN_C)] : 0.f;
    }
    __syncthreads();
    float b1j = b1[t];
    float w[IN_C];
#pragma unroll
    for (int k = 0; k < IN_C; k++) w[k] = W1s[k * HID + t];
    float sum = 0.f, sq = 0.f;
    for (int r = 0; r < G1_ROWS; r++) {
        int row = row0 + r;
        if (row >= N_NODES) break;
        float h0 = b1j, h1 = 0.f, h2 = 0.f;
#pragma unroll
        for (int k = 0; k < IN_C; k += 3) {
            h0 += xas[r * IN_C + k] * w[k];
            if (k + 1 < IN_C) h1 += xas[r * IN_C + k + 1] * w[k + 1];
            if (k + 2 < IN_C) h2 += xas[r * IN_C + k + 2] * w[k + 2];
        }
        float h = h0 + h1 + h2;
        g_h1h[(long)row * HID + t] = __float2half(h);
        sum += h;
        sq += h * h;
    }
    atomicAdd(&g_stat1[t], sum);
    atomicAdd(&g_stat1[HID + t], sq);
}

// z' = dinv * (relu(bn1(h1)) @ W2); BN1 affine in prologue
#define TCBM 128
#define TCBK 32
#define AS_S 36
#define BS_S 136
__global__ __launch_bounds__(256) void k_gemm2(const float* __restrict__ W2,
                                               const float* __restrict__ g1,
                                               const float* __restrict__ be1) {
    __shared__ unsigned As[TCBM * AS_S];
    __shared__ unsigned Bs[TCBK * BS_S];
    __shared__ float s1s[HID], t1s[HID];
    const int t = threadIdx.x;
    const int lane = t & 31;
    const int wid = t >> 5;
    const int gid = lane >> 2;
    const int t4 = lane & 3;
    const int warp_row = (wid & 3) * 32;
    const int warp_col = (wid >> 2) * 64;
    const int row0 = blockIdx.x * TCBM;

    {
        float mean = g_stat1[t] / (float)N_NODES;
        float var = g_stat1[HID + t] / (float)N_NODES - mean * mean;
        var = fmaxf(var, 0.f);
        float sc = rsqrtf(var + BN_EPS) * g1[t];
        s1s[t] = sc;
        t1s[t] = be1[t] - mean * sc;
    }

    float acc[2][8][4];
#pragma unroll
    for (int r = 0; r < 2; r++)
#pragma unroll
        for (int c = 0; c < 8; c++)
#pragma unroll
            for (int i = 0; i < 4; i++) acc[r][c][i] = 0.f;
    __syncthreads();

    for (int kt = 0; kt < HID / TCBK; kt++) {
#pragma unroll
        for (int it = 0; it < 2; it++) {
            int q = t + it * 256;
            int row = q >> 2;
            int col8 = (q & 3) * 8;
            int kg = kt * TCBK + col8;
            int grow = row0 + row;
            uint4 raw = make_uint4(0u, 0u, 0u, 0u);
            if (grow < N_NODES)
                raw = *reinterpret_cast<const uint4*>(&g_h1h[(long)grow * HID + kg]);
            const __half2* hp = reinterpret_cast<const __half2*>(&raw);
#pragma unroll
            for (int u = 0; u < 4; u++) {
                float2 f = __half22float2(hp[u]);
                int k0 = kg + u * 2;
                As[row * AS_S + col8 + u * 2 + 0] =
                    f2tf(fmaxf(f.x * s1s[k0 + 0] + t1s[k0 + 0], 0.f));
                As[row * AS_S + col8 + u * 2 + 1] =
                    f2tf(fmaxf(f.y * s1s[k0 + 1] + t1s[k0 + 1], 0.f));
            }
        }
#pragma unroll
        for (int it = 0; it < 4; it++) {
            int q = t + it * 256;
            int kb = q >> 5;
            int col4 = (q & 31) * 4;
            float4 v = *reinterpret_cast<const float4*>(&W2[(long)(kt * TCBK + kb) * OUTF + col4]);
            Bs[kb * BS_S + col4 + 0] = f2tf(v.x);
            Bs[kb * BS_S + col4 + 1] = f2tf(v.y);
            Bs[kb * BS_S + col4 + 2] = f2tf(v.z);
            Bs[kb * BS_S + col4 + 3] = f2tf(v.w);
        }
        __syncthreads();
#pragma unroll
        for (int ks = 0; ks < TCBK / 8; ks++) {
            unsigned a[2][4], b[8][2];
#pragma unroll
            for (int r = 0; r < 2; r++) {
                int rb = (warp_row + r * 16 + gid) * AS_S + ks * 8 + t4;
                a[r][0] = As[rb];
                a[r][1] = As[rb + 8 * AS_S];
                a[r][2] = As[rb + 4];
                a[r][3] = As[rb + 8 * AS_S + 4];
            }
#pragma unroll
            for (int c = 0; c < 8; c++) {
                int cb = (ks * 8 + t4) * BS_S + warp_col + c * 8 + gid;
                b[c][0] = Bs[cb];
                b[c][1] = Bs[cb + 4 * BS_S];
            }
#pragma unroll
            for (int r = 0; r < 2; r++)
#pragma unroll
                for (int c = 0; c < 8; c++) mma_tf32(acc[r][c], a[r], b[c]);
        }
        __syncthreads();
    }
#pragma unroll
    for (int r = 0; r < 2; r++) {
        int rowA = row0 + warp_row + r * 16 + gid;
        int rowB = rowA + 8;
        float dA = (rowA < N_NODES) ? g_dinv[rowA] : 0.f;
        float dB = (rowB < N_NODES) ? g_dinv[rowB] : 0.f;
#pragma unroll
        for (int c = 0; c < 8; c++) {
            int col = warp_col + c * 8 + t4 * 2;
            if (rowA < N_NODES)
                *reinterpret_cast<__half2*>(&g_zh[(long)rowA * OUTF + col]) =
                    __floats2half2_rn(dA * acc[r][c][0], dA * acc[r][c][1]);
            if (rowB < N_NODES)
                *reinterpret_cast<__half2*>(&g_zh[(long)rowB * OUTF + col]) =
                    __floats2half2_rn(dB * acc[r][c][2], dB * acc[r][c][3]);
        }
    }
}

// agg2: thread-per-column, 8 nodes/block, 8-edge unroll (explicit scalars)
#define A2_NPB 8
__global__ __launch_bounds__(128) void k_agg2(const float* __restrict__ b2) {
    int j = threadIdx.x;
    int n0 = blockIdx.x * A2_NPB;
    float b2j = b2[j];
    float bs = 0.f, bq = 0.f;
#pragma unroll 1
    for (int u = 0; u < A2_NPB; u++) {
        int n = n0 + u;
        int s = g_rowptr[n], e = g_rowptr[n + 1];
        float acc = __half2float(g_zh[(long)n * OUTF + j]);
        int p = s;
#pragma unroll 1
        for (; p + 8 <= e; p += 8) {
            int s0 = g_csr_src[p + 0], s1 = g_csr_src[p + 1];
            int s2 = g_csr_src[p + 2], s3 = g_csr_src[p + 3];
            int s4 = g_csr_src[p + 4], s5 = g_csr_src[p + 5];
            int s6 = g_csr_src[p + 6], s7 = g_csr_src[p + 7];
            float z0 = __half2float(g_zh[(long)s0 * OUTF + j]);
            float z1 = __half2float(g_zh[(long)s1 * OUTF + j]);
            float z2 = __half2float(g_zh[(long)s2 * OUTF + j]);
            float z3 = __half2float(g_zh[(long)s3 * OUTF + j]);
            float z4 = __half2float(g_zh[(long)s4 * OUTF + j]);
            float z5 = __half2float(g_zh[(long)s5 * OUTF + j]);
            float z6 = __half2float(g_zh[(long)s6 * OUTF + j]);
            float z7 = __half2float(g_zh[(long)s7 * OUTF + j]);
            acc += ((z0 + z1) + (z2 + z3)) + ((z4 + z5) + (z6 + z7));
        }
        for (; p < e; p++)
            acc += __half2float(g_zh[(long)g_csr_src[p] * OUTF + j]);
        float dn = g_dinv[n];
        float val = dn * acc + b2j;
        g_h2[(long)n * OUTF + j] = val;
        bs += val;
        bq += val * val;
    }
    atomicAdd(&g_stat2[j], bs);
    atomicAdd(&g_stat2[OUTF + j], bq);
}

// pool + BN2 affine + L2 normalize
__global__ __launch_bounds__(128) void k_pool(const float* __restrict__ g2,
                                              const float* __restrict__ be2,
                                              float* __restrict__ out) {
    int g = blockIdx.x;
    int j = threadIdx.x;
    float mean = g_stat2[j] / (float)N_NODES;
    float var = g_stat2[OUTF + j] / (float)N_NODES - mean * mean;
    var = fmaxf(var, 0.f);
    float sc = rsqrtf(var + BN_EPS) * g2[j];
    float sh = be2[j] - mean * sc;
    int s = g_gstart[g], e = g_gstart[g + 1];
    float acc = 0.f;
    for (int i = s; i < e; i++) acc += g_h2[(long)i * OUTF + j];
    int cnt = e - s;
    float y = 0.f;
    if (cnt > 0) {
        float p = acc / (float)cnt;
        y = p * sc + sh;
    }
    float v = y * y;
#pragma unroll
    for (int off = 16; off > 0; off >>= 1) v += __shfl_xor_sync(0xffffffffu, v, off);
    __shared__ float ws[4];
    if ((j & 31) == 0) ws[j >> 5] = v;
    __syncthreads();
    float ss = ws[0] + ws[1] + ws[2] + ws[3];
    float nrm = sqrtf(ss);
    out[g * OUTF + j] = y / fmaxf(nrm, 1e-12f);
}

// ---------------- launch ----------------
extern "C" void kernel_launch(void* const* d_in, const int* in_sizes, int n_in,
                              void* d_out, int out_size) {
    const float* x   = (const float*)d_in[0];
    const float* W1  = (const float*)d_in[1];
    const float* b1  = (const float*)d_in[2];
    const float* g1  = (const float*)d_in[3];
    const float* be1 = (const float*)d_in[4];
    const float* W2  = (const float*)d_in[5];
    const float* b2  = (const float*)d_in[6];
    const float* g2  = (const float*)d_in[7];
    const float* be2 = (const float*)d_in[8];
    const int* edge  = (const int*)d_in[9];
    const int* batch = (const int*)d_in[10];
    float* out = (float*)d_out;

    const int TB = 256;
    int nb_N = (N_NODES + TB - 1) / TB;
    int nb_E4 = (N_EDGES / 4 + TB - 1) / TB;
    int nb_fill = ((N_NODES + 1 > N_EDGES / 4 ? N_NODES + 1 : N_EDGES / 4) + TB - 1) / TB;

    k_init<<<nb_N, TB>>>();
    k_count<<<nb_E4, TB>>>(edge);
    k_scan1<<<SCAN_NB, SCAN_B>>>();
    k_scan2<<<1, 128>>>();
    k_scan3<<<SCAN_NB, SCAN_B>>>(x);
    k_fill<<<nb_fill, TB>>>(edge, batch);
    k_agg1<<<nb_N, TB>>>();
    k_gemm1<<<(N_NODES + G1_ROWS - 1) / G1_ROWS, 256>>>(W1, b1);
    k_gemm2<<<(N_NODES + TCBM - 1) / TCBM, 256>>>(W2, g1, be1);
    k_agg2<<<N_NODES / A2_NPB, 128>>>(b2);
    k_pool<<<N_GRAPHS, 128>>>(g2, be2, out);
}

// round 16
// speedup vs baseline: 1.1046x; 1.0052x over previous
#include <cuda_runtime.h>
#include <cuda_fp16.h>
#include <math.h>

#define N_NODES 100000
#define N_EDGES 1600000
#define N_GRAPHS 2000
#define IN_C 9
#define HID 256
#define OUTF 128
#define BN_EPS 1e-5f

#define SCAN_B 1024
#define SCAN_NB ((N_NODES + SCAN_B - 1) / SCAN_B)   // 98

// ---------------- scratch ----------------
__device__ float g_dinv[N_NODES];
__device__ int   g_cnt[N_NODES];
__device__ int   g_rowptr[N_NODES + 1];
__device__ int   g_bsum[SCAN_NB];
__device__ int   g_csr_src[N_EDGES];
__device__ float g_xp[N_NODES * IN_C];
__device__ float g_xa[N_NODES * IN_C];
__device__ __align__(16) __half g_h1h[N_NODES * HID];
__device__ __align__(16) __half g_zh [N_NODES * OUTF];
__device__ float g_pool[N_GRAPHS * OUTF];   // per-graph pooled sums (pre-BN2)
__device__ float g_stat1[2 * HID];
__device__ float g_stat2[2 * OUTF];
__device__ int   g_gstart[N_GRAPHS + 1];

// ---------------- helpers ----------------
__device__ __forceinline__ unsigned f2tf(float f) {
    unsigned r;
    asm("cvt.rna.tf32.f32 %0, %1;" : "=r"(r) : "f"(f));
    return r;
}
__device__ __forceinline__ void mma_tf32(float* d, const unsigned* a, const unsigned* b) {
    asm volatile(
        "mma.sync.aligned.m16n8k8.row.col.f32.tf32.tf32.f32 "
        "{%0,%1,%2,%3}, {%4,%5,%6,%7}, {%8,%9}, {%0,%1,%2,%3};"
        : "+f"(d[0]), "+f"(d[1]), "+f"(d[2]), "+f"(d[3])
        : "r"(a[0]), "r"(a[1]), "r"(a[2]), "r"(a[3]), "r"(b[0]), "r"(b[1]));
}

// ---------------- kernels ----------------

__global__ void k_init() {
    int i = blockIdx.x * blockDim.x + threadIdx.x;
    int total = gridDim.x * blockDim.x;
    if (i < N_NODES) g_cnt[i] = 0;
    if (i < 2 * HID) g_stat1[i] = 0.f;
    if (i < 2 * OUTF) g_stat2[i] = 0.f;
    for (int p = i; p < N_GRAPHS * OUTF; p += total) g_pool[p] = 0.f;
}

// 4 edges per thread via int4
__global__ void k_count(const int* __restrict__ edge) {
    int q = blockIdx.x * blockDim.x + threadIdx.x;
    int e4 = q * 4;
    if (e4 >= N_EDGES) return;
    int4 d = *reinterpret_cast<const int4*>(&edge[N_EDGES + e4]);
    atomicAdd(&g_cnt[d.x], 1);
    atomicAdd(&g_cnt[d.y], 1);
    atomicAdd(&g_cnt[d.z], 1);
    atomicAdd(&g_cnt[d.w], 1);
}

__global__ __launch_bounds__(SCAN_B) void k_scan1() {
    __shared__ int sh[SCAN_B];
    int t = threadIdx.x;
    int i = blockIdx.x * SCAN_B + t;
    int c = (i < N_NODES) ? g_cnt[i] : 0;
    if (i < N_NODES) g_dinv[i] = rsqrtf((float)(c + 1));
    sh[t] = c;
    __syncthreads();
#pragma unroll
    for (int off = 1; off < SCAN_B; off <<= 1) {
        int v = sh[t];
        int add = (t >= off) ? sh[t - off] : 0;
        __syncthreads();
        sh[t] = v + add;
        __syncthreads();
    }
    if (i < N_NODES) g_rowptr[i] = sh[t] - c;
    if (t == SCAN_B - 1) g_bsum[blockIdx.x] = sh[t];
}

__global__ void k_scan2() {
    __shared__ int sh[128];
    int t = threadIdx.x;
    int v = (t < SCAN_NB) ? g_bsum[t] : 0;
    sh[t] = v;
    __syncthreads();
#pragma unroll
    for (int off = 1; off < 128; off <<= 1) {
        int x = sh[t];
        int add = (t >= off) ? sh[t - off] : 0;
        __syncthreads();
        sh[t] = x + add;
        __syncthreads();
    }
    if (t < SCAN_NB) g_bsum[t] = sh[t] - v;
}

__global__ __launch_bounds__(SCAN_B) void k_scan3(const float* __restrict__ x) {
    int i = blockIdx.x * SCAN_B + threadIdx.x;
    if (i < N_NODES) {
        int rp = g_rowptr[i] + g_bsum[blockIdx.x];
        g_rowptr[i] = rp;
        g_cnt[i] = rp;
        float dn = g_dinv[i];
        const float* xr = x + (long)i * IN_C;
        float* xw = g_xp + (long)i * IN_C;
#pragma unroll
        for (int k = 0; k < IN_C; k++) xw[k] = dn * xr[k];
    }
    if (i == 0) g_rowptr[N_NODES] = N_EDGES;
}

// fill CSR: 4 edges/thread via int4; fused gstart on the same grid
__global__ void k_fill(const int* __restrict__ edge, const int* __restrict__ batch) {
    int q = blockIdx.x * blockDim.x + threadIdx.x;
    int e4 = q * 4;
    if (e4 < N_EDGES) {
        int4 s = *reinterpret_cast<const int4*>(&edge[e4]);
        int4 d = *reinterpret_cast<const int4*>(&edge[N_EDGES + e4]);
        int p0 = atomicAdd(&g_cnt[d.x], 1); g_csr_src[p0] = s.x;
        int p1 = atomicAdd(&g_cnt[d.y], 1); g_csr_src[p1] = s.y;
        int p2 = atomicAdd(&g_cnt[d.z], 1); g_csr_src[p2] = s.z;
        int p3 = atomicAdd(&g_cnt[d.w], 1); g_csr_src[p3] = s.w;
    }
    if (q <= N_NODES) {
        int b = (q < N_NODES) ? batch[q] : N_GRAPHS;
        int bp = (q > 0) ? batch[q - 1] : -1;
        for (int g = bp + 1; g <= b && g <= N_GRAPHS; g++) g_gstart[g] = q;
    }
}

// xa[n] = dinv[n] * (sum_{sn} x'[sn] + x'[n])
__global__ void k_agg1() {
    int n = blockIdx.x * blockDim.x + threadIdx.x;
    if (n >= N_NODES) return;
    float acc[IN_C];
    const float* xn = g_xp + (long)n * IN_C;
#pragma unroll
    for (int k = 0; k < IN_C; k++) acc[k] = xn[k];
    int s = g_rowptr[n], e = g_rowptr[n + 1];
    for (int p = s; p < e; p++) {
        int sn = g_csr_src[p];
        const float* xr = g_xp + (long)sn * IN_C;
#pragma unroll
        for (int k = 0; k < IN_C; k++) acc[k] += xr[k];
    }
    float dn = g_dinv[n];
#pragma unroll
    for (int k = 0; k < IN_C; k++) g_xa[n * IN_C + k] = dn * acc[k];
}

// h1 = xa @ W1 + b1 (raw fp16), fused BN1 stats. 256 rows/block.
#define G1_ROWS 256
__global__ __launch_bounds__(256) void k_gemm1(const float* __restrict__ W1,
                                               const float* __restrict__ b1) {
    __shared__ float W1s[IN_C * HID];
    __shared__ float xas[G1_ROWS * IN_C];
    int t = threadIdx.x;
    int row0 = blockIdx.x * G1_ROWS;
    for (int i = t; i < IN_C * HID; i += 256) W1s[i] = W1[i];
    for (int i = t; i < G1_ROWS * IN_C; i += 256) {
        int r = row0 + i / IN_C;
        xas[i] = (r < N_NODES) ? g_xa[(long)r * IN_C + (i % IN_C)] : 0.f;
    }
    __syncthreads();
    float b1j = b1[t];
    float w[IN_C];
#pragma unroll
    for (int k = 0; k < IN_C; k++) w[k] = W1s[k * HID + t];
    float sum = 0.f, sq = 0.f;
    for (int r = 0; r < G1_ROWS; r++) {
        int row = row0 + r;
        if (row >= N_NODES) break;
        float h0 = b1j, h1 = 0.f, h2 = 0.f;
#pragma unroll
        for (int k = 0; k < IN_C; k += 3) {
            h0 += xas[r * IN_C + k] * w[k];
            if (k + 1 < IN_C) h1 += xas[r * IN_C + k + 1] * w[k + 1];
            if (k + 2 < IN_C) h2 += xas[r * IN_C + k + 2] * w[k + 2];
        }
        float h = h0 + h1 + h2;
        g_h1h[(long)row * HID + t] = __float2half(h);
        sum += h;
        sq += h * h;
    }
    atomicAdd(&g_stat1[t], sum);
    atomicAdd(&g_stat1[HID + t], sq);
}

// z' = dinv * (relu(bn1(h1)) @ W2); BN1 affine in prologue
#define TCBM 128
#define TCBK 32
#define AS_S 36
#define BS_S 136
__global__ __launch_bounds__(256) void k_gemm2(const float* __restrict__ W2,
                                               const float* __restrict__ g1,
                                               const float* __restrict__ be1) {
    __shared__ unsigned As[TCBM * AS_S];
    __shared__ unsigned Bs[TCBK * BS_S];
    __shared__ float s1s[HID], t1s[HID];
    const int t = threadIdx.x;
    const int lane = t & 31;
    const int wid = t >> 5;
    const int gid = lane >> 2;
    const int t4 = lane & 3;
    const int warp_row = (wid & 3) * 32;
    const int warp_col = (wid >> 2) * 64;
    const int row0 = blockIdx.x * TCBM;

    {
        float mean = g_stat1[t] / (float)N_NODES;
        float var = g_stat1[HID + t] / (float)N_NODES - mean * mean;
        var = fmaxf(var, 0.f);
        float sc = rsqrtf(var + BN_EPS) * g1[t];
        s1s[t] = sc;
        t1s[t] = be1[t] - mean * sc;
    }

    float acc[2][8][4];
#pragma unroll
    for (int r = 0; r < 2; r++)
#pragma unroll
        for (int c = 0; c < 8; c++)
#pragma unroll
            for (int i = 0; i < 4; i++) acc[r][c][i] = 0.f;
    __syncthreads();

    for (int kt = 0; kt < HID / TCBK; kt++) {
#pragma unroll
        for (int it = 0; it < 2; it++) {
            int q = t + it * 256;
            int row = q >> 2;
            int col8 = (q & 3) * 8;
            int kg = kt * TCBK + col8;
            int grow = row0 + row;
            uint4 raw = make_uint4(0u, 0u, 0u, 0u);
            if (grow < N_NODES)
                raw = *reinterpret_cast<const uint4*>(&g_h1h[(long)grow * HID + kg]);
            const __half2* hp = reinterpret_cast<const __half2*>(&raw);
#pragma unroll
            for (int u = 0; u < 4; u++) {
                float2 f = __half22float2(hp[u]);
                int k0 = kg + u * 2;
                As[row * AS_S + col8 + u * 2 + 0] =
                    f2tf(fmaxf(f.x * s1s[k0 + 0] + t1s[k0 + 0], 0.f));
                As[row * AS_S + col8 + u * 2 + 1] =
                    f2tf(fmaxf(f.y * s1s[k0 + 1] + t1s[k0 + 1], 0.f));
            }
        }
#pragma unroll
        for (int it = 0; it < 4; it++) {
            int q = t + it * 256;
            int kb = q >> 5;
            int col4 = (q & 31) * 4;
            float4 v = *reinterpret_cast<const float4*>(&W2[(long)(kt * TCBK + kb) * OUTF + col4]);
            Bs[kb * BS_S + col4 + 0] = f2tf(v.x);
            Bs[kb * BS_S + col4 + 1] = f2tf(v.y);
            Bs[kb * BS_S + col4 + 2] = f2tf(v.z);
            Bs[kb * BS_S + col4 + 3] = f2tf(v.w);
        }
        __syncthreads();
#pragma unroll
        for (int ks = 0; ks < TCBK / 8; ks++) {
            unsigned a[2][4], b[8][2];
#pragma unroll
            for (int r = 0; r < 2; r++) {
                int rb = (warp_row + r * 16 + gid) * AS_S + ks * 8 + t4;
                a[r][0] = As[rb];
                a[r][1] = As[rb + 8 * AS_S];
                a[r][2] = As[rb + 4];
                a[r][3] = As[rb + 8 * AS_S + 4];
            }
#pragma unroll
            for (int c = 0; c < 8; c++) {
                int cb = (ks * 8 + t4) * BS_S + warp_col + c * 8 + gid;
                b[c][0] = Bs[cb];
                b[c][1] = Bs[cb + 4 * BS_S];
            }
#pragma unroll
            for (int r = 0; r < 2; r++)
#pragma unroll
                for (int c = 0; c < 8; c++) mma_tf32(acc[r][c], a[r], b[c]);
        }
        __syncthreads();
    }
#pragma unroll
    for (int r = 0; r < 2; r++) {
        int rowA = row0 + warp_row + r * 16 + gid;
        int rowB = rowA + 8;
        float dA = (rowA < N_NODES) ? g_dinv[rowA] : 0.f;
        float dB = (rowB < N_NODES) ? g_dinv[rowB] : 0.f;
#pragma unroll
        for (int c = 0; c < 8; c++) {
            int col = warp_col + c * 8 + t4 * 2;
            if (rowA < N_NODES)
                *reinterpret_cast<__half2*>(&g_zh[(long)rowA * OUTF + col]) =
                    __floats2half2_rn(dA * acc[r][c][0], dA * acc[r][c][1]);
            if (rowB < N_NODES)
                *reinterpret_cast<__half2*>(&g_zh[(long)rowB * OUTF + col]) =
                    __floats2half2_rn(dB * acc[r][c][2], dB * acc[r][c][3]);
        }
    }
}

// agg2 + pooled accumulation: h2 never materialized. Per-graph run sums are
// flushed with one atomicAdd per (run, column). BN2 stats fused as before.
#define A2_NPB 8
__global__ __launch_bounds__(128) void k_agg2(const float* __restrict__ b2,
                                              const int* __restrict__ batch) {
    int j = threadIdx.x;
    int n0 = blockIdx.x * A2_NPB;
    float b2j = b2[j];
    float bs = 0.f, bq = 0.f;
    float runacc = 0.f;
    int rung = batch[n0];
#pragma unroll 1
    for (int u = 0; u < A2_NPB; u++) {
        int n = n0 + u;
        int s = g_rowptr[n], e = g_rowptr[n + 1];
        float acc = __half2float(g_zh[(long)n * OUTF + j]);
        int p = s;
        for (; p + 4 <= e; p += 4) {
            int s0 = g_csr_src[p + 0], s1 = g_csr_src[p + 1];
            int s2 = g_csr_src[p + 2], s3 = g_csr_src[p + 3];
            float z0 = __half2float(g_zh[(long)s0 * OUTF + j]);
            float z1 = __half2float(g_zh[(long)s1 * OUTF + j]);
            float z2 = __half2float(g_zh[(long)s2 * OUTF + j]);
            float z3 = __half2float(g_zh[(long)s3 * OUTF + j]);
            acc += z0 + z1 + z2 + z3;
        }
        for (; p < e; p++)
            acc += __half2float(g_zh[(long)g_csr_src[p] * OUTF + j]);
        float dn = g_dinv[n];
        float val = dn * acc + b2j;
        bs += val;
        bq += val * val;
        int gi = batch[n];
        if (gi != rung) {
            atomicAdd(&g_pool[rung * OUTF + j], runacc);
            runacc = 0.f;
            rung = gi;
        }
        runacc += val;
    }
    atomicAdd(&g_pool[rung * OUTF + j], runacc);
    atomicAdd(&g_stat2[j], bs);
    atomicAdd(&g_stat2[OUTF + j], bq);
}

// out: BN2 affine (commuted past mean-pool) + L2 normalize, from g_pool
__global__ __launch_bounds__(128) void k_out(const float* __restrict__ g2,
                                             const float* __restrict__ be2,
                                             float* __restrict__ out) {
    int g = blockIdx.x;
    int j = threadIdx.x;
    float mean = g_stat2[j] / (float)N_NODES;
    float var = g_stat2[OUTF + j] / (float)N_NODES - mean * mean;
    var = fmaxf(var, 0.f);
    float sc = rsqrtf(var + BN_EPS) * g2[j];
    float sh = be2[j] - mean * sc;
    int cnt = g_gstart[g + 1] - g_gstart[g];
    float y = 0.f;
    if (cnt > 0) {
        float p = g_pool[g * OUTF + j] / (float)cnt;
        y = p * sc + sh;
    }
    float v = y * y;
#pragma unroll
    for (int off = 16; off > 0; off >>= 1) v += __shfl_xor_sync(0xffffffffu, v, off);
    __shared__ float ws[4];
    if ((j & 31) == 0) ws[j >> 5] = v;
    __syncthreads();
    float ss = ws[0] + ws[1] + ws[2] + ws[3];
    float nrm = sqrtf(ss);
    out[g * OUTF + j] = y / fmaxf(nrm, 1e-12f);
}

// ---------------- launch ----------------
extern "C" void kernel_launch(void* const* d_in, const int* in_sizes, int n_in,
                              void* d_out, int out_size) {
    const float* x   = (const float*)d_in[0];
    const float* W1  = (const float*)d_in[1];
    const float* b1  = (const float*)d_in[2];
    const float* g1  = (const float*)d_in[3];
    const float* be1 = (const float*)d_in[4];
    const float* W2  = (const float*)d_in[5];
    const float* b2  = (const float*)d_in[6];
    const float* g2  = (const float*)d_in[7];
    const float* be2 = (const float*)d_in[8];
    const int* edge  = (const int*)d_in[9];
    const int* batch = (const int*)d_in[10];
    float* out = (float*)d_out;

    const int TB = 256;
    int nb_N = (N_NODES + TB - 1) / TB;
    int nb_E4 = (N_EDGES / 4 + TB - 1) / TB;
    int nb_fill = ((N_NODES + 1 > N_EDGES / 4 ? N_NODES + 1 : N_EDGES / 4) + TB - 1) / TB;

    k_init<<<nb_N, TB>>>();
    k_count<<<nb_E4, TB>>>(edge);
    k_scan1<<<SCAN_NB, SCAN_B>>>();
    k_scan2<<<1, 128>>>();
    k_scan3<<<SCAN_NB, SCAN_B>>>(x);
    k_fill<<<nb_fill, TB>>>(edge, batch);
    k_agg1<<<nb_N, TB>>>();
    k_gemm1<<<(N_NODES + G1_ROWS - 1) / G1_ROWS, 256>>>(W1, b1);
    k_gemm2<<<(N_NODES + TCBM - 1) / TCBM, 256>>>(W2, g1, be1);
    k_agg2<<<N_NODES / A2_NPB, 128>>>(b2, batch);
    k_out<<<N_GRAPHS, 128>>>(g2, be2, out);
}

// round 17
// speedup vs baseline: 1.1875x; 1.0751x over previous
#include <cuda_runtime.h>
#include <cuda_fp16.h>
#include <math.h>

#define N_NODES 100000
#define N_EDGES 1600000
#define N_GRAPHS 2000
#define IN_C 9
#define HID 256
#define OUTF 128
#define BN_EPS 1e-5f

#define SCAN_B 1024
#define SCAN_NB ((N_NODES + SCAN_B - 1) / SCAN_B)   // 98

// ---------------- scratch ----------------
__device__ float g_dinv[N_NODES];
__device__ int   g_cnt[N_NODES];
__device__ int   g_rowptr[N_NODES + 1];
__device__ int   g_bsum[SCAN_NB];
__device__ int   g_csr_src[N_EDGES];
__device__ float g_xp[N_NODES * IN_C];
__device__ float g_xa[N_NODES * IN_C];
__device__ __align__(16) __half g_h1h[N_NODES * HID];
__device__ __align__(16) __half g_zh [N_NODES * OUTF];
__device__ __align__(16) __half g_w2h[OUTF * HID];     // W2^T fp16 [n][k]
__device__ float g_pool[N_GRAPHS * OUTF];
__device__ float g_stat1[2 * HID];
__device__ float g_stat2[2 * OUTF];
__device__ int   g_gstart[N_GRAPHS + 1];

// ---------------- helpers ----------------
__device__ __forceinline__ void mma_f16(float* d, const unsigned* a, const unsigned* b) {
    asm volatile(
        "mma.sync.aligned.m16n8k16.row.col.f32.f16.f16.f32 "
        "{%0,%1,%2,%3}, {%4,%5,%6,%7}, {%8,%9}, {%0,%1,%2,%3};"
        : "+f"(d[0]), "+f"(d[1]), "+f"(d[2]), "+f"(d[3])
        : "r"(a[0]), "r"(a[1]), "r"(a[2]), "r"(a[3]), "r"(b[0]), "r"(b[1]));
}

// ---------------- kernels ----------------

// init scratch + transpose W2 -> fp16 [n][k]
__global__ void k_init(const float* __restrict__ W2) {
    int i = blockIdx.x * blockDim.x + threadIdx.x;
    int total = gridDim.x * blockDim.x;
    if (i < N_NODES) g_cnt[i] = 0;
    if (i < 2 * HID) g_stat1[i] = 0.f;
    if (i < 2 * OUTF) g_stat2[i] = 0.f;
    for (int p = i; p < N_GRAPHS * OUTF; p += total) g_pool[p] = 0.f;
    for (int p = i; p < HID * OUTF; p += total) {
        int k = p >> 7;          // 0..255
        int n = p & 127;         // 0..127
        g_w2h[n * HID + k] = __float2half(W2[p]);
    }
}

// 4 edges per thread via int4
__global__ void k_count(const int* __restrict__ edge) {
    int q = blockIdx.x * blockDim.x + threadIdx.x;
    int e4 = q * 4;
    if (e4 >= N_EDGES) return;
    int4 d = *reinterpret_cast<const int4*>(&edge[N_EDGES + e4]);
    atomicAdd(&g_cnt[d.x], 1);
    atomicAdd(&g_cnt[d.y], 1);
    atomicAdd(&g_cnt[d.z], 1);
    atomicAdd(&g_cnt[d.w], 1);
}

__global__ __launch_bounds__(SCAN_B) void k_scan1() {
    __shared__ int sh[SCAN_B];
    int t = threadIdx.x;
    int i = blockIdx.x * SCAN_B + t;
    int c = (i < N_NODES) ? g_cnt[i] : 0;
    if (i < N_NODES) g_dinv[i] = rsqrtf((float)(c + 1));
    sh[t] = c;
    __syncthreads();
#pragma unroll
    for (int off = 1; off < SCAN_B; off <<= 1) {
        int v = sh[t];
        int add = (t >= off) ? sh[t - off] : 0;
        __syncthreads();
        sh[t] = v + add;
        __syncthreads();
    }
    if (i < N_NODES) g_rowptr[i] = sh[t] - c;
    if (t == SCAN_B - 1) g_bsum[blockIdx.x] = sh[t];
}

__global__ void k_scan2() {
    __shared__ int sh[128];
    int t = threadIdx.x;
    int v = (t < SCAN_NB) ? g_bsum[t] : 0;
    sh[t] = v;
    __syncthreads();
#pragma unroll
    for (int off = 1; off < 128; off <<= 1) {
        int x = sh[t];
        int add = (t >= off) ? sh[t - off] : 0;
        __syncthreads();
        sh[t] = x + add;
        __syncthreads();
    }
    if (t < SCAN_NB) g_bsum[t] = sh[t] - v;
}

__global__ __launch_bounds__(SCAN_B) void k_scan3(const float* __restrict__ x) {
    int i = blockIdx.x * SCAN_B + threadIdx.x;
    if (i < N_NODES) {
        int rp = g_rowptr[i] + g_bsum[blockIdx.x];
        g_rowptr[i] = rp;
        g_cnt[i] = rp;
        float dn = g_dinv[i];
        const float* xr = x + (long)i * IN_C;
        float* xw = g_xp + (long)i * IN_C;
#pragma unroll
        for (int k = 0; k < IN_C; k++) xw[k] = dn * xr[k];
    }
    if (i == 0) g_rowptr[N_NODES] = N_EDGES;
}

// fill CSR: 4 edges/thread via int4; fused gstart on the same grid
__global__ void k_fill(const int* __restrict__ edge, const int* __restrict__ batch) {
    int q = blockIdx.x * blockDim.x + threadIdx.x;
    int e4 = q * 4;
    if (e4 < N_EDGES) {
        int4 s = *reinterpret_cast<const int4*>(&edge[e4]);
        int4 d = *reinterpret_cast<const int4*>(&edge[N_EDGES + e4]);
        int p0 = atomicAdd(&g_cnt[d.x], 1); g_csr_src[p0] = s.x;
        int p1 = atomicAdd(&g_cnt[d.y], 1); g_csr_src[p1] = s.y;
        int p2 = atomicAdd(&g_cnt[d.z], 1); g_csr_src[p2] = s.z;
        int p3 = atomicAdd(&g_cnt[d.w], 1); g_csr_src[p3] = s.w;
    }
    if (q <= N_NODES) {
        int b = (q < N_NODES) ? batch[q] : N_GRAPHS;
        int bp = (q > 0) ? batch[q - 1] : -1;
        for (int g = bp + 1; g <= b && g <= N_GRAPHS; g++) g_gstart[g] = q;
    }
}

// xa[n] = dinv[n] * (sum_{sn} x'[sn] + x'[n])
__global__ void k_agg1() {
    int n = blockIdx.x * blockDim.x + threadIdx.x;
    if (n >= N_NODES) return;
    float acc[IN_C];
    const float* xn = g_xp + (long)n * IN_C;
#pragma unroll
    for (int k = 0; k < IN_C; k++) acc[k] = xn[k];
    int s = g_rowptr[n], e = g_rowptr[n + 1];
    for (int p = s; p < e; p++) {
        int sn = g_csr_src[p];
        const float* xr = g_xp + (long)sn * IN_C;
#pragma unroll
        for (int k = 0; k < IN_C; k++) acc[k] += xr[k];
    }
    float dn = g_dinv[n];
#pragma unroll
    for (int k = 0; k < IN_C; k++) g_xa[n * IN_C + k] = dn * acc[k];
}

// h1 = xa @ W1 + b1 (raw fp16), fused BN1 stats. 256 rows/block.
#define G1_ROWS 256
__global__ __launch_bounds__(256) void k_gemm1(const float* __restrict__ W1,
                                               const float* __restrict__ b1) {
    __shared__ float W1s[IN_C * HID];
    __shared__ float xas[G1_ROWS * IN_C];
    int t = threadIdx.x;
    int row0 = blockIdx.x * G1_ROWS;
    for (int i = t; i < IN_C * HID; i += 256) W1s[i] = W1[i];
    for (int i = t; i < G1_ROWS * IN_C; i += 256) {
        int r = row0 + i / IN_C;
        xas[i] = (r < N_NODES) ? g_xa[(long)r * IN_C + (i % IN_C)] : 0.f;
    }
    __syncthreads();
    float b1j = b1[t];
    float w[IN_C];
#pragma unroll
    for (int k = 0; k < IN_C; k++) w[k] = W1s[k * HID + t];
    float sum = 0.f, sq = 0.f;
    for (int r = 0; r < G1_ROWS; r++) {
        int row = row0 + r;
        if (row >= N_NODES) break;
        float h0 = b1j, h1 = 0.f, h2 = 0.f;
#pragma unroll
        for (int k = 0; k < IN_C; k += 3) {
            h0 += xas[r * IN_C + k] * w[k];
            if (k + 1 < IN_C) h1 += xas[r * IN_C + k + 1] * w[k + 1];
            if (k + 2 < IN_C) h2 += xas[r * IN_C + k + 2] * w[k + 2];
        }
        float h = h0 + h1 + h2;
        g_h1h[(long)row * HID + t] = __float2half(h);
        sum += h;
        sq += h * h;
    }
    atomicAdd(&g_stat1[t], sum);
    atomicAdd(&g_stat1[HID + t], sq);
}

// z' = dinv * (relu(bn1(h1)) @ W2) via fp16 mma m16n8k16 (R8 fragment layout).
// BN1 affine from stats in prologue; A stored post-BN fp16; B from g_w2h.
#define TCBM 128
#define TCBK 32
#define SM_S 40    // halves; word stride 20 -> conflict-free fragments (R8-proven)
__global__ __launch_bounds__(256) void k_gemm2(const float* __restrict__ g1,
                                               const float* __restrict__ be1) {
    __shared__ __align__(16) __half As[TCBM * SM_S];
    __shared__ __align__(16) __half Bs[OUTF * SM_S];
    __shared__ float s1s[HID], t1s[HID];
    const int t = threadIdx.x;
    const int lane = t & 31;
    const int wid = t >> 5;
    const int gid = lane >> 2;
    const int t4 = lane & 3;
    const int warp_row = (wid & 3) * 32;
    const int warp_col = (wid >> 2) * 64;
    const int row0 = blockIdx.x * TCBM;
    const unsigned* As32 = reinterpret_cast<const unsigned*>(As);
    const unsigned* Bs32 = reinterpret_cast<const unsigned*>(Bs);

    {
        float mean = g_stat1[t] / (float)N_NODES;
        float var = g_stat1[HID + t] / (float)N_NODES - mean * mean;
        var = fmaxf(var, 0.f);
        float sc = rsqrtf(var + BN_EPS) * g1[t];
        s1s[t] = sc;
        t1s[t] = be1[t] - mean * sc;
    }

    float acc[2][8][4];
#pragma unroll
    for (int r = 0; r < 2; r++)
#pragma unroll
        for (int c = 0; c < 8; c++)
#pragma unroll
            for (int i = 0; i < 4; i++) acc[r][c][i] = 0.f;
    __syncthreads();

    for (int kt = 0; kt < HID / TCBK; kt++) {
        // A chunk: 128 rows x 32 halves; BN+relu in fp32, store fp16
#pragma unroll
        for (int it = 0; it < 2; it++) {
            int q = t + it * 256;
            int row = q >> 2;
            int k8 = (q & 3) * 8;
            int kg = kt * TCBK + k8;
            int grow = row0 + row;
            uint4 raw = make_uint4(0u, 0u, 0u, 0u);
            if (grow < N_NODES)
                raw = *reinterpret_cast<const uint4*>(&g_h1h[(long)grow * HID + kg]);
            const __half2* hp = reinterpret_cast<const __half2*>(&raw);
            uint4 outw;
            unsigned* ow = reinterpret_cast<unsigned*>(&outw);
#pragma unroll
            for (int u = 0; u < 4; u++) {
                float2 f = __half22float2(hp[u]);
                int k0 = kg + u * 2;
                float e0 = fmaxf(f.x * s1s[k0 + 0] + t1s[k0 + 0], 0.f);
                float e1 = fmaxf(f.y * s1s[k0 + 1] + t1s[k0 + 1], 0.f);
                __half2 h2v = __floats2half2_rn(e0, e1);
                ow[u] = *reinterpret_cast<unsigned*>(&h2v);
            }
            *reinterpret_cast<uint4*>(&As[row * SM_S + k8]) = outw;
        }
        // B chunk: 128 cols x 32 halves, straight copy from W2^T fp16
#pragma unroll
        for (int it = 0; it < 2; it++) {
            int q = t + it * 256;
            int n = q >> 2;
            int k8 = (q & 3) * 8;
            uint4 v = *reinterpret_cast<const uint4*>(&g_w2h[n * HID + kt * TCBK + k8]);
            *reinterpret_cast<uint4*>(&Bs[n * SM_S + k8]) = v;
        }
        __syncthreads();
#pragma unroll
        for (int ks = 0; ks < 2; ks++) {     // two k16 steps per 32-chunk
            unsigned a[2][4], b[8][2];
#pragma unroll
            for (int r = 0; r < 2; r++) {
                int rb = (warp_row + r * 16 + gid) * (SM_S / 2) + ks * 8 + t4;
                a[r][0] = As32[rb];
                a[r][1] = As32[rb + 8 * (SM_S / 2)];
                a[r][2] = As32[rb + 4];
                a[r][3] = As32[rb + 8 * (SM_S / 2) + 4];
            }
#pragma unroll
            for (int c = 0; c < 8; c++) {
                int cb = (warp_col + c * 8 + gid) * (SM_S / 2) + ks * 8 + t4;
                b[c][0] = Bs32[cb];
                b[c][1] = Bs32[cb + 4];
            }
#pragma unroll
            for (int r = 0; r < 2; r++)
#pragma unroll
                for (int c = 0; c < 8; c++) mma_f16(acc[r][c], a[r], b[c]);
        }
        __syncthreads();
    }
#pragma unroll
    for (int r = 0; r < 2; r++) {
        int rowA = row0 + warp_row + r * 16 + gid;
        int rowB = rowA + 8;
        float dA = (rowA < N_NODES) ? g_dinv[rowA] : 0.f;
        float dB = (rowB < N_NODES) ? g_dinv[rowB] : 0.f;
#pragma unroll
        for (int c = 0; c < 8; c++) {
            int col = warp_col + c * 8 + t4 * 2;
            if (rowA < N_NODES)
                *reinterpret_cast<__half2*>(&g_zh[(long)rowA * OUTF + col]) =
                    __floats2half2_rn(dA * acc[r][c][0], dA * acc[r][c][1]);
            if (rowB < N_NODES)
                *reinterpret_cast<__half2*>(&g_zh[(long)rowB * OUTF + col]) =
                    __floats2half2_rn(dB * acc[r][c][2], dB * acc[r][c][3]);
        }
    }
}

// agg2 + pooled accumulation; fused BN2 stats
#define A2_NPB 8
__global__ __launch_bounds__(128) void k_agg2(const float* __restrict__ b2,
                                              const int* __restrict__ batch) {
    int j = threadIdx.x;
    int n0 = blockIdx.x * A2_NPB;
    float b2j = b2[j];
    float bs = 0.f, bq = 0.f;
    float runacc = 0.f;
    int rung = batch[n0];
#pragma unroll 1
    for (int u = 0; u < A2_NPB; u++) {
        int n = n0 + u;
        int s = g_rowptr[n], e = g_rowptr[n + 1];
        float acc = __half2float(g_zh[(long)n * OUTF + j]);
        int p = s;
        for (; p + 4 <= e; p += 4) {
            int s0 = g_csr_src[p + 0], s1 = g_csr_src[p + 1];
            int s2 = g_csr_src[p + 2], s3 = g_csr_src[p + 3];
            float z0 = __half2float(g_zh[(long)s0 * OUTF + j]);
            float z1 = __half2float(g_zh[(long)s1 * OUTF + j]);
            float z2 = __half2float(g_zh[(long)s2 * OUTF + j]);
            float z3 = __half2float(g_zh[(long)s3 * OUTF + j]);
            acc += z0 + z1 + z2 + z3;
        }
        for (; p < e; p++)
            acc += __half2float(g_zh[(long)g_csr_src[p] * OUTF + j]);
        float dn = g_dinv[n];
        float val = dn * acc + b2j;
        bs += val;
        bq += val * val;
        int gi = batch[n];
        if (gi != rung) {
            atomicAdd(&g_pool[rung * OUTF + j], runacc);
            runacc = 0.f;
            rung = gi;
        }
        runacc += val;
    }
    atomicAdd(&g_pool[rung * OUTF + j], runacc);
    atomicAdd(&g_stat2[j], bs);
    atomicAdd(&g_stat2[OUTF + j], bq);
}

// out: BN2 affine + mean + L2 normalize from g_pool
__global__ __launch_bounds__(128) void k_out(const float* __restrict__ g2,
                                             const float* __restrict__ be2,
                                             float* __restrict__ out) {
    int g = blockIdx.x;
    int j = threadIdx.x;
    float mean = g_stat2[j] / (float)N_NODES;
    float var = g_stat2[OUTF + j] / (float)N_NODES - mean * mean;
    var = fmaxf(var, 0.f);
    float sc = rsqrtf(var + BN_EPS) * g2[j];
    float sh = be2[j] - mean * sc;
    int cnt = g_gstart[g + 1] - g_gstart[g];
    float y = 0.f;
    if (cnt > 0) {
        float p = g_pool[g * OUTF + j] / (float)cnt;
        y = p * sc + sh;
    }
    float v = y * y;
#pragma unroll
    for (int off = 16; off > 0; off >>= 1) v += __shfl_xor_sync(0xffffffffu, v, off);
    __shared__ float ws[4];
    if ((j & 31) == 0) ws[j >> 5] = v;
    __syncthreads();
    float ss = ws[0] + ws[1] + ws[2] + ws[3];
    float nrm = sqrtf(ss);
    out[g * OUTF + j] = y / fmaxf(nrm, 1e-12f);
}

// ---------------- launch ----------------
extern "C" void kernel_launch(void* const* d_in, const int* in_sizes, int n_in,
                              void* d_out, int out_size) {
    const float* x   = (const float*)d_in[0];
    const float* W1  = (const float*)d_in[1];
    const float* b1  = (const float*)d_in[2];
    const float* g1  = (const float*)d_in[3];
    const float* be1 = (const float*)d_in[4];
    const float* W2  = (const float*)d_in[5];
    const float* b2  = (const float*)d_in[6];
    const float* g2  = (const float*)d_in[7];
    const float* be2 = (const float*)d_in[8];
    const int* edge  = (const int*)d_in[9];
    const int* batch = (const int*)d_in[10];
    float* out = (float*)d_out;

    const int TB = 256;
    int nb_N = (N_NODES + TB - 1) / TB;
    int nb_E4 = (N_EDGES / 4 + TB - 1) / TB;
    int nb_fill = ((N_NODES + 1 > N_EDGES / 4 ? N_NODES + 1 : N_EDGES / 4) + TB - 1) / TB;

    k_init<<<nb_N, TB>>>(W2);
    k_count<<<nb_E4, TB>>>(edge);
    k_scan1<<<SCAN_NB, SCAN_B>>>();
    k_scan2<<<1, 128>>>();
    k_scan3<<<SCAN_NB, SCAN_B>>>(x);
    k_fill<<<nb_fill, TB>>>(edge, batch);
    k_agg1<<<nb_N, TB>>>();
    k_gemm1<<<(N_NODES + G1_ROWS - 1) / G1_ROWS, 256>>>(W1, b1);
    k_gemm2<<<(N_NODES + TCBM - 1) / TCBM, 256>>>(g1, be1);
    k_agg2<<<N_NODES / A2_NPB, 128>>>(b2, batch);
    k_out<<<N_GRAPHS, 128>>>(g2, be2, out);
}